// round 8
// baseline (speedup 1.0000x reference)
#include <cuda_runtime.h>
#include <cuda_fp16.h>
#include <stdint.h>

#define NSEQ 512
#define SCALE_F 0.04419417382415922f

// ---------------------------------------------------------------------------
// Scratch (device globals: allocation-free rule)
// ---------------------------------------------------------------------------
__device__ __align__(128) __half d_qkv [16L * 512 * 2048];        // [b][n][2048]: q|k|v
__device__ __align__(128) __half d_sc  [16L * 8  * 512 * 512];    // [b][g][n][m]
__device__ __align__(128) __half d_aw  [16L * 16 * 512 * 512];    // [b][l][n][m]
__device__ __align__(128) __half d_o   [16L * 512 * 1024];        // [b][n][l*64+d]
__device__ __align__(128) __half d_wqkv[512 * 2048];              // [k][n] n-major
__device__ __align__(128) __half d_wouth[1024 * 512];             // [k][n] n-major
__device__ __align__(128) float  d_bqkv[2048];                    // 0 | 0 | bv

// MLP weights in constant memory (uniform access -> const port, not L1)
__constant__ float cW1[128];
__constant__ float cW2[256];
__constant__ float cb1[16];
__constant__ float cb2[16];
__constant__ float csig[8];

// ---------------------------------------------------------------------------
__device__ __forceinline__ void mma16(float* c, const uint32_t* a, const uint32_t* b) {
    asm volatile(
        "mma.sync.aligned.m16n8k16.row.col.f32.f16.f16.f32 "
        "{%0,%1,%2,%3}, {%4,%5,%6,%7}, {%8,%9}, {%0,%1,%2,%3};\n"
        : "+f"(c[0]), "+f"(c[1]), "+f"(c[2]), "+f"(c[3])
        : "r"(a[0]), "r"(a[1]), "r"(a[2]), "r"(a[3]), "r"(b[0]), "r"(b[1]));
}

// Generic batched fp16 GEMM, fp32 accumulate.  C[M,N] = A[M,K] @ B (+bias[col])
// AH: 1 = A is half, 0 = A is float (converted while staging)
// TB: 1 = B stored [N][K] row-major (K-major, "B^T"), 0 = B stored [K][N] row-major
// OH: 1 = C stored half, 0 = C stored float
// Tile: 128x64, kc=64, 8 warps (4 M x 2 N), warp tile 32x32.
template<int AH, int TB, int OH>
__global__ __launch_bounds__(256) void gemm_h(
    const void* __restrict__ Av, const __half* __restrict__ B,
    void* __restrict__ Cv, const float* __restrict__ bias,
    int M, int N, int K, int lda, int ldb, int ldc,
    int innerShift, long sAb, long sAj, long sBb, long sBj, long sCb, long sCj)
{
    __shared__ __align__(16) __half As[128][72];
    __shared__ __align__(16) __half Bs[64][72];

    const int tid = threadIdx.x;
    const int tilesN = N >> 6;
    const int tm = blockIdx.x / tilesN, tn = blockIdx.x % tilesN;
    const int row0 = tm * 128, col0 = tn * 64;

    const int z = blockIdx.y;
    const int bb = z >> innerShift, jj = z & ((1 << innerShift) - 1);
    const float*  Af = (const float*)Av  + bb * sAb + jj * sAj;
    const __half* Ah = (const __half*)Av + bb * sAb + jj * sAj;
    const __half* Bb = B + bb * sBb + jj * sBj;

    const int lane = tid & 31, wid = tid >> 5;
    const int wm = wid & 3, wn = wid >> 2;
    const int g = lane >> 2, t = lane & 3;

    float c[2][4][4];
    #pragma unroll
    for (int mi = 0; mi < 2; mi++)
        #pragma unroll
        for (int ni = 0; ni < 4; ni++)
            #pragma unroll
            for (int ci = 0; ci < 4; ci++) c[mi][ni][ci] = 0.0f;

    for (int k0 = 0; k0 < K; k0 += 64) {
        // ---- stage A: 128 x 64 halves ----
        #pragma unroll
        for (int i = 0; i < 4; i++) {
            int f = tid + i * 256;
            int r = f >> 3, c8 = (f & 7) * 8;
            if (AH) {
                uint4 u = *(const uint4*)(Ah + (size_t)(row0 + r) * lda + k0 + c8);
                *(uint4*)&As[r][c8] = u;
            } else {
                const float4* p = (const float4*)(Af + (size_t)(row0 + r) * lda + k0 + c8);
                float4 u0 = p[0], u1 = p[1];
                __half h8[8];
                h8[0] = __float2half(u0.x); h8[1] = __float2half(u0.y);
                h8[2] = __float2half(u0.z); h8[3] = __float2half(u0.w);
                h8[4] = __float2half(u1.x); h8[5] = __float2half(u1.y);
                h8[6] = __float2half(u1.z); h8[7] = __float2half(u1.w);
                *(uint4*)&As[r][c8] = *(uint4*)h8;
            }
        }
        // ---- stage B: 64 x 64 halves -> Bs[n][k] ----
        if (TB) {
            #pragma unroll
            for (int i = 0; i < 2; i++) {
                int f = tid + i * 256;
                int r = f >> 3, c8 = (f & 7) * 8;
                uint4 u = *(const uint4*)(Bb + (size_t)(col0 + r) * ldb + k0 + c8);
                *(uint4*)&Bs[r][c8] = u;
            }
        } else {
            #pragma unroll
            for (int it2 = 0; it2 < 2; it2++) {
                int n = tid & 63;
                int kg = ((tid >> 6) << 3) + it2 * 32;
                __half h8[8];
                #pragma unroll
                for (int j = 0; j < 8; j++)
                    h8[j] = Bb[(size_t)(k0 + kg + j) * ldb + col0 + n];
                *(uint4*)&Bs[n][kg] = *(uint4*)h8;
            }
        }
        __syncthreads();
        // ---- mainloop: 4 k16 steps ----
        #pragma unroll
        for (int ks = 0; ks < 4; ks++) {
            int kb = ks * 16;
            uint32_t af[2][4], bf[4][2];
            #pragma unroll
            for (int mi = 0; mi < 2; mi++) {
                int rb = wm * 32 + mi * 16 + g;
                af[mi][0] = *(const uint32_t*)&As[rb    ][kb + 2 * t];
                af[mi][1] = *(const uint32_t*)&As[rb + 8][kb + 2 * t];
                af[mi][2] = *(const uint32_t*)&As[rb    ][kb + 2 * t + 8];
                af[mi][3] = *(const uint32_t*)&As[rb + 8][kb + 2 * t + 8];
            }
            #pragma unroll
            for (int ni = 0; ni < 4; ni++) {
                int cb = wn * 32 + ni * 8 + g;
                bf[ni][0] = *(const uint32_t*)&Bs[cb][kb + 2 * t];
                bf[ni][1] = *(const uint32_t*)&Bs[cb][kb + 2 * t + 8];
            }
            #pragma unroll
            for (int mi = 0; mi < 2; mi++)
                #pragma unroll
                for (int ni = 0; ni < 4; ni++)
                    mma16(c[mi][ni], af[mi], bf[ni]);
        }
        __syncthreads();
    }

    // ---- epilogue ----
    #pragma unroll
    for (int mi = 0; mi < 2; mi++)
        #pragma unroll
        for (int ni = 0; ni < 4; ni++) {
            int row = row0 + wm * 32 + mi * 16 + g;
            int col = col0 + wn * 32 + ni * 8 + 2 * t;
            float b0f = 0.0f, b1f = 0.0f;
            if (bias) { b0f = bias[col]; b1f = bias[col + 1]; }
            float v0 = c[mi][ni][0] + b0f, v1 = c[mi][ni][1] + b1f;
            float v2 = c[mi][ni][2] + b0f, v3 = c[mi][ni][3] + b1f;
            if (OH) {
                __half* Ch = (__half*)Cv + bb * sCb + jj * sCj;
                *(__half2*)(Ch + (size_t)row * ldc + col)       = __floats2half2_rn(v0, v1);
                *(__half2*)(Ch + (size_t)(row + 8) * ldc + col) = __floats2half2_rn(v2, v3);
            } else {
                float* Cf = (float*)Cv + bb * sCb + jj * sCj;
                *(float2*)(Cf + (size_t)row * ldc + col)       = make_float2(v0, v1);
                *(float2*)(Cf + (size_t)(row + 8) * ldc + col) = make_float2(v2, v3);
            }
        }
}

// ---------------------------------------------------------------------------
// Weight prepack: fp32 -> fp16, fuse Wq|Wk|Wv, zero-padded bias
// ---------------------------------------------------------------------------
__global__ __launch_bounds__(256) void prepack(
    const float* __restrict__ Wq, const float* __restrict__ Wk,
    const float* __restrict__ Wv, const float* __restrict__ bv,
    const float* __restrict__ Wout)
{
    int idx = blockIdx.x * 256 + threadIdx.x;       // 0 .. 1048575
    {
        int k = idx >> 11, c = idx & 2047;
        float val;
        if (c < 512)       val = Wq[k * 512 + c];
        else if (c < 1024) val = Wk[k * 512 + (c - 512)];
        else               val = Wv[k * 1024 + (c - 1024)];
        d_wqkv[idx] = __float2half(val);
    }
    if (idx < 1024 * 512) d_wouth[idx] = __float2half(Wout[idx]);
    if (idx < 2048)       d_bqkv[idx] = (idx < 1024) ? 0.0f : bv[idx - 1024];
}

// ---------------------------------------------------------------------------
// mish(x) = x * (u^2+2u)/(u^2+2u+2), u = e^x   (exact identity)
// ---------------------------------------------------------------------------
__device__ __forceinline__ float mish_f(float x) {
    if (x > 30.0f) return x;
    float u = __expf(x);
    float w = u * u + 2.0f * u;
    return x * w * (1.0f / (w + 2.0f));
}

// Fused: noise + head-mix MLP (mish) + prior + softmax over L -> d_aw (half)
// One thread handles TWO adjacent m positions. MLP weights come from
// __constant__ memory (const port) instead of shared memory (L1 port).
__global__ __launch_bounds__(256) void k_mid(
    const float* __restrict__ prior, const float* __restrict__ eps)
{
    const size_t idx = (size_t)blockIdx.x * 256 + threadIdx.x; // 0 .. 2^21-1
    const int mp = (int)(idx & 255);
    const int n  = (int)((idx >> 8) & 511);
    const int b  = (int)(idx >> 17);
    const int m  = mp * 2;

    // scores: 8 half2 loads (two positions each)
    float s[2][8];
    #pragma unroll
    for (int gi = 0; gi < 8; gi++) {
        __half2 v = *(const __half2*)(d_sc + ((size_t)(b * 8 + gi) * 512 + n) * 512 + m);
        float2 vf = __half22float2(v);
        s[0][gi] = vf.x; s[1][gi] = vf.y;
    }
    // eps: 16 consecutive floats (8 per position)
    const float4* ep = (const float4*)(eps + ((size_t)(b * 512 + n) * 512 + m) * 8);
    float e[16];
    #pragma unroll
    for (int i = 0; i < 4; i++) {
        float4 t4 = ep[i];
        e[4 * i + 0] = t4.x; e[4 * i + 1] = t4.y;
        e[4 * i + 2] = t4.z; e[4 * i + 3] = t4.w;
    }

    const float* prBase = prior + ((size_t)(b * 16) * 512 + n) * 512 + m;

    float fo[2][16];
    #pragma unroll
    for (int p = 0; p < 2; p++) {
        bool pad = true;
        #pragma unroll
        for (int gi = 0; gi < 8; gi++) pad = pad && (s[p][gi] == 0.0f);

        float av[8];
        #pragma unroll
        for (int gi = 0; gi < 8; gi++) {
            float sg = csig[gi];
            av[gi] = fmaf(sg * sg, e[p * 8 + gi], s[p][gi]);
        }
        float h[16];
        #pragma unroll
        for (int l = 0; l < 16; l++) {
            float acc = cb1[l];
            #pragma unroll
            for (int gi = 0; gi < 8; gi++) acc = fmaf(av[gi], cW1[gi * 16 + l], acc);
            h[l] = mish_f(acc);
        }
        float mx = -1e30f;
        #pragma unroll
        for (int l = 0; l < 16; l++) {
            float acc = cb2[l];
            #pragma unroll
            for (int j = 0; j < 16; j++) acc = fmaf(h[j], cW2[j * 16 + l], acc);
            float logit = fmaf(acc, SCALE_F, __ldg(prBase + (size_t)l * 262144 + p));
            fo[p][l] = logit;
            mx = fmaxf(mx, logit);
        }
        float sum = 0.0f;
        #pragma unroll
        for (int l = 0; l < 16; l++) { fo[p][l] = __expf(fo[p][l] - mx); sum += fo[p][l]; }
        float inv = pad ? 0.0f : (1.0f / sum);
        #pragma unroll
        for (int l = 0; l < 16; l++) fo[p][l] *= inv;
    }
    // store: 16 half2 (both positions)
    #pragma unroll
    for (int l = 0; l < 16; l++)
        *(__half2*)(d_aw + ((size_t)(b * 16 + l) * 512 + n) * 512 + m) =
            __floats2half2_rn(fo[0][l], fo[1][l]);
}

// ---------------------------------------------------------------------------
extern "C" void kernel_launch(void* const* d_in, const int* in_sizes, int n_in,
                              void* d_out, int out_size)
{
    const float* x     = (const float*)d_in[0];
    const float* prior = (const float*)d_in[1];
    const float* eps   = (const float*)d_in[2];
    const float* Wq    = (const float*)d_in[3];
    const float* Wk    = (const float*)d_in[4];
    const float* Wv    = (const float*)d_in[5];
    const float* bv    = (const float*)d_in[6];
    const float* sigma = (const float*)d_in[7];
    const float* Wp1   = (const float*)d_in[8];
    const float* bp1   = (const float*)d_in[9];
    const float* Wp2   = (const float*)d_in[10];
    const float* bp2   = (const float*)d_in[11];
    const float* Wout  = (const float*)d_in[12];
    float* out = (float*)d_out;

    __half *qkv, *sc, *aw, *o, *wqkv, *wouth;
    float* bqkv;
    cudaGetSymbolAddress((void**)&qkv,   d_qkv);
    cudaGetSymbolAddress((void**)&sc,    d_sc);
    cudaGetSymbolAddress((void**)&aw,    d_aw);
    cudaGetSymbolAddress((void**)&o,     d_o);
    cudaGetSymbolAddress((void**)&wqkv,  d_wqkv);
    cudaGetSymbolAddress((void**)&wouth, d_wouth);
    cudaGetSymbolAddress((void**)&bqkv,  d_bqkv);

    const long S   = 512L * 512L;        // 262144
    const long SQ  = 512L * 2048L;       // per-batch qkv stride

    // 0a. MLP weights -> constant bank (D2D, graph-capturable)
    cudaMemcpyToSymbolAsync(cW1,  Wp1,   128 * sizeof(float), 0, cudaMemcpyDeviceToDevice);
    cudaMemcpyToSymbolAsync(cW2,  Wp2,   256 * sizeof(float), 0, cudaMemcpyDeviceToDevice);
    cudaMemcpyToSymbolAsync(cb1,  bp1,    16 * sizeof(float), 0, cudaMemcpyDeviceToDevice);
    cudaMemcpyToSymbolAsync(cb2,  bp2,    16 * sizeof(float), 0, cudaMemcpyDeviceToDevice);
    cudaMemcpyToSymbolAsync(csig, sigma,   8 * sizeof(float), 0, cudaMemcpyDeviceToDevice);

    // 0b. weight prepack (fp32 -> fp16)
    prepack<<<4096, 256>>>(Wq, Wk, Wv, bv, Wout);

    // 1. qkv = x @ [Wq|Wk|Wv] (+bias on v cols)   M=8192 N=2048 K=512
    gemm_h<0, 0, 1><<<dim3(64 * 32, 1), 256>>>(
        x, wqkv, qkv, bqkv,
        8192, 2048, 512, 512, 2048, 2048, 0, 0, 0, 0, 0, 0, 0);

    // 2. scores[b,g] = q_g @ k_g^T   (batch 128)  M=512 N=512 K=64
    gemm_h<1, 1, 1><<<dim3(4 * 8, 128), 256>>>(
        qkv, qkv + 512, sc, nullptr,
        512, 512, 64, 2048, 2048, 512,
        3, SQ, 64, SQ, 64, 8 * S, S);

    // 3. noise + MLP + prior + softmax(L)  (2 positions per thread)
    k_mid<<<8192, 256>>>(prior, eps);

    // 4. o[b,:,l,:] = aw[b,l] @ v[b,:,l,:]   (batch 256)  M=512 N=64 K=512
    gemm_h<1, 0, 1><<<dim3(4 * 1, 256), 256>>>(
        aw, qkv + 1024, o, nullptr,
        512, 64, 512, 512, 2048, 1024,
        4, 16 * S, S, SQ, 64, 512L * 1024L, 64);

    // 5. out = o @ Wout   M=8192 N=512 K=1024
    gemm_h<1, 0, 0><<<dim3(64 * 8, 1), 256>>>(
        o, wouth, out, nullptr,
        8192, 512, 1024, 1024, 512, 512, 0, 0, 0, 0, 0, 0, 0);
}

// round 11
// speedup vs baseline: 1.0948x; 1.0948x over previous
#include <cuda_runtime.h>
#include <cuda_fp16.h>
#include <stdint.h>

#define NSEQ 512
#define SCALE_F 0.04419417382415922f

// ---------------------------------------------------------------------------
// Scratch (device globals: allocation-free rule)
// ---------------------------------------------------------------------------
__device__ __align__(128) __half d_qkv [16L * 512 * 2048];        // [b][n][2048]: q|k|v
__device__ __align__(128) __half d_sc  [16L * 8  * 512 * 512];    // [b][g][n][m]
__device__ __align__(128) __half d_aw  [16L * 16 * 512 * 512];    // [b][l][n][m]
__device__ __align__(128) __half d_o   [16L * 512 * 1024];        // [b][n][l*64+d]
__device__ __align__(128) __half d_wqkv[512 * 2048];              // [k][n] n-major
__device__ __align__(128) __half d_wouth[1024 * 512];             // [k][n] n-major
__device__ __align__(128) float  d_bqkv[2048];                    // 0 | 0 | bv

// MLP weights in constant memory (read once per thread into fragments)
__constant__ float cW1[128];
__constant__ float cW2[256];
__constant__ float cb1[16];
__constant__ float cb2[16];
__constant__ float csig[8];

// ---------------------------------------------------------------------------
__device__ __forceinline__ void mma16(float* c, const uint32_t* a, const uint32_t* b) {
    asm volatile(
        "mma.sync.aligned.m16n8k16.row.col.f32.f16.f16.f32 "
        "{%0,%1,%2,%3}, {%4,%5,%6,%7}, {%8,%9}, {%0,%1,%2,%3};\n"
        : "+f"(c[0]), "+f"(c[1]), "+f"(c[2]), "+f"(c[3])
        : "r"(a[0]), "r"(a[1]), "r"(a[2]), "r"(a[3]), "r"(b[0]), "r"(b[1]));
}
__device__ __forceinline__ uint32_t h2u(__half2 v) { return *(uint32_t*)&v; }
__device__ __forceinline__ uint32_t f2h2u(float lo, float hi) {
    __half2 h = __floats2half2_rn(lo, hi);
    return *(uint32_t*)&h;
}

// Generic batched fp16 GEMM, fp32 accumulate.  C[M,N] = A[M,K] @ B (+bias[col])
// AH: 1 = A is half, 0 = A is float (converted while staging)
// TB: 1 = B stored [N][K] row-major (K-major, "B^T"), 0 = B stored [K][N] row-major
// OH: 1 = C stored half, 0 = C stored float
// Tile: 128x64, kc=64, 8 warps (4 M x 2 N), warp tile 32x32.
template<int AH, int TB, int OH>
__global__ __launch_bounds__(256) void gemm_h(
    const void* __restrict__ Av, const __half* __restrict__ B,
    void* __restrict__ Cv, const float* __restrict__ bias,
    int M, int N, int K, int lda, int ldb, int ldc,
    int innerShift, long sAb, long sAj, long sBb, long sBj, long sCb, long sCj)
{
    __shared__ __align__(16) __half As[128][72];
    __shared__ __align__(16) __half Bs[64][72];

    const int tid = threadIdx.x;
    const int tilesN = N >> 6;
    const int tm = blockIdx.x / tilesN, tn = blockIdx.x % tilesN;
    const int row0 = tm * 128, col0 = tn * 64;

    const int z = blockIdx.y;
    const int bb = z >> innerShift, jj = z & ((1 << innerShift) - 1);
    const float*  Af = (const float*)Av  + bb * sAb + jj * sAj;
    const __half* Ah = (const __half*)Av + bb * sAb + jj * sAj;
    const __half* Bb = B + bb * sBb + jj * sBj;

    const int lane = tid & 31, wid = tid >> 5;
    const int wm = wid & 3, wn = wid >> 2;
    const int g = lane >> 2, t = lane & 3;

    float c[2][4][4];
    #pragma unroll
    for (int mi = 0; mi < 2; mi++)
        #pragma unroll
        for (int ni = 0; ni < 4; ni++)
            #pragma unroll
            for (int ci = 0; ci < 4; ci++) c[mi][ni][ci] = 0.0f;

    for (int k0 = 0; k0 < K; k0 += 64) {
        // ---- stage A: 128 x 64 halves ----
        #pragma unroll
        for (int i = 0; i < 4; i++) {
            int f = tid + i * 256;
            int r = f >> 3, c8 = (f & 7) * 8;
            if (AH) {
                uint4 u = *(const uint4*)(Ah + (size_t)(row0 + r) * lda + k0 + c8);
                *(uint4*)&As[r][c8] = u;
            } else {
                const float4* p = (const float4*)(Af + (size_t)(row0 + r) * lda + k0 + c8);
                float4 u0 = p[0], u1 = p[1];
                __half h8[8];
                h8[0] = __float2half(u0.x); h8[1] = __float2half(u0.y);
                h8[2] = __float2half(u0.z); h8[3] = __float2half(u0.w);
                h8[4] = __float2half(u1.x); h8[5] = __float2half(u1.y);
                h8[6] = __float2half(u1.z); h8[7] = __float2half(u1.w);
                *(uint4*)&As[r][c8] = *(uint4*)h8;
            }
        }
        // ---- stage B: 64 x 64 halves -> Bs[n][k] ----
        if (TB) {
            #pragma unroll
            for (int i = 0; i < 2; i++) {
                int f = tid + i * 256;
                int r = f >> 3, c8 = (f & 7) * 8;
                uint4 u = *(const uint4*)(Bb + (size_t)(col0 + r) * ldb + k0 + c8);
                *(uint4*)&Bs[r][c8] = u;
            }
        } else {
            #pragma unroll
            for (int it2 = 0; it2 < 2; it2++) {
                int n = tid & 63;
                int kg = ((tid >> 6) << 3) + it2 * 32;
                __half h8[8];
                #pragma unroll
                for (int j = 0; j < 8; j++)
                    h8[j] = Bb[(size_t)(k0 + kg + j) * ldb + col0 + n];
                *(uint4*)&Bs[n][kg] = *(uint4*)h8;
            }
        }
        __syncthreads();
        // ---- mainloop: 4 k16 steps ----
        #pragma unroll
        for (int ks = 0; ks < 4; ks++) {
            int kb = ks * 16;
            uint32_t af[2][4], bf[4][2];
            #pragma unroll
            for (int mi = 0; mi < 2; mi++) {
                int rb = wm * 32 + mi * 16 + g;
                af[mi][0] = *(const uint32_t*)&As[rb    ][kb + 2 * t];
                af[mi][1] = *(const uint32_t*)&As[rb + 8][kb + 2 * t];
                af[mi][2] = *(const uint32_t*)&As[rb    ][kb + 2 * t + 8];
                af[mi][3] = *(const uint32_t*)&As[rb + 8][kb + 2 * t + 8];
            }
            #pragma unroll
            for (int ni = 0; ni < 4; ni++) {
                int cb = wn * 32 + ni * 8 + g;
                bf[ni][0] = *(const uint32_t*)&Bs[cb][kb + 2 * t];
                bf[ni][1] = *(const uint32_t*)&Bs[cb][kb + 2 * t + 8];
            }
            #pragma unroll
            for (int mi = 0; mi < 2; mi++)
                #pragma unroll
                for (int ni = 0; ni < 4; ni++)
                    mma16(c[mi][ni], af[mi], bf[ni]);
        }
        __syncthreads();
    }

    // ---- epilogue ----
    #pragma unroll
    for (int mi = 0; mi < 2; mi++)
        #pragma unroll
        for (int ni = 0; ni < 4; ni++) {
            int row = row0 + wm * 32 + mi * 16 + g;
            int col = col0 + wn * 32 + ni * 8 + 2 * t;
            float b0f = 0.0f, b1f = 0.0f;
            if (bias) { b0f = bias[col]; b1f = bias[col + 1]; }
            float v0 = c[mi][ni][0] + b0f, v1 = c[mi][ni][1] + b1f;
            float v2 = c[mi][ni][2] + b0f, v3 = c[mi][ni][3] + b1f;
            if (OH) {
                __half* Ch = (__half*)Cv + bb * sCb + jj * sCj;
                *(__half2*)(Ch + (size_t)row * ldc + col)       = __floats2half2_rn(v0, v1);
                *(__half2*)(Ch + (size_t)(row + 8) * ldc + col) = __floats2half2_rn(v2, v3);
            } else {
                float* Cf = (float*)Cv + bb * sCb + jj * sCj;
                *(float2*)(Cf + (size_t)row * ldc + col)       = make_float2(v0, v1);
                *(float2*)(Cf + (size_t)(row + 8) * ldc + col) = make_float2(v2, v3);
            }
        }
}

// ---------------------------------------------------------------------------
// Weight prepack: fp32 -> fp16, fuse Wq|Wk|Wv, zero-padded bias
// ---------------------------------------------------------------------------
__global__ __launch_bounds__(256) void prepack(
    const float* __restrict__ Wq, const float* __restrict__ Wk,
    const float* __restrict__ Wv, const float* __restrict__ bv,
    const float* __restrict__ Wout)
{
    int idx = blockIdx.x * 256 + threadIdx.x;       // 0 .. 1048575
    {
        int k = idx >> 11, c = idx & 2047;
        float val;
        if (c < 512)       val = Wq[k * 512 + c];
        else if (c < 1024) val = Wk[k * 512 + (c - 512)];
        else               val = Wv[k * 1024 + (c - 1024)];
        d_wqkv[idx] = __float2half(val);
    }
    if (idx < 1024 * 512) d_wouth[idx] = __float2half(Wout[idx]);
    if (idx < 2048)       d_bqkv[idx] = (idx < 1024) ? 0.0f : bv[idx - 1024];
}

// ---------------------------------------------------------------------------
// mish(x) = x * (u^2+2u)/(u^2+2u+2), u = e^x   (exact identity, fp32)
// ---------------------------------------------------------------------------
__device__ __forceinline__ float mish_f(float x) {
    float u = __expf(x);
    float w = fmaf(u, u, 2.0f * u);
    float r = x * w * __frcp_rn(w + 2.0f);
    return (x > 20.0f) ? x : r;
}

// ---------------------------------------------------------------------------
// k_mid_mma: noise + head-mix MLP on TENSOR CORES + prior + softmax(L)
// One warp handles a strip of 16 consecutive m positions (fixed b,n) per tile.
// Layer1: mma m16n8k16, A = av[m][g] (K padded 8->16 zeros), B = W1 fragment.
// mish on fp32 C-frag, cvt -> layer2 A-frag directly (identical lane layout).
// Layer2: mma, + bias (as C init) -> *SCALE + prior -> softmax over L via
// quad butterfly shuffles. Weights live in registers; zero per-tile wt loads.
// All per-value state in compile-time-indexed register arrays (no addr-of-local).
// ---------------------------------------------------------------------------
__global__ __launch_bounds__(256) void k_mid_mma(
    const float* __restrict__ prior, const float* __restrict__ eps)
{
    const int lane = threadIdx.x & 31;
    const int g = lane >> 2, t = lane & 3;
    const int warpGlobal = (blockIdx.x << 3) + (threadIdx.x >> 5);

    // ---- weight fragments (once per thread) ----
    uint32_t w1f[2], w2f[2][2];
    float b1v[2][2], b2v[2][2];
    #pragma unroll
    for (int c = 0; c < 2; c++) {
        w1f[c]    = f2h2u(cW1[(2*t)  *16 + 8*c + g], cW1[(2*t+1)*16 + 8*c + g]);
        w2f[c][0] = f2h2u(cW2[(2*t)  *16 + 8*c + g], cW2[(2*t+1)*16 + 8*c + g]);
        w2f[c][1] = f2h2u(cW2[(2*t+8)*16 + 8*c + g], cW2[(2*t+9)*16 + 8*c + g]);
        b1v[c][0] = cb1[8*c + 2*t]; b1v[c][1] = cb1[8*c + 2*t + 1];
        b2v[c][0] = cb2[8*c + 2*t]; b2v[c][1] = cb2[8*c + 2*t + 1];
    }
    const float sg0 = csig[2*t], sg1 = csig[2*t+1];
    const __half2 sig2 = __floats2half2_rn(sg0 * sg0, sg1 * sg1);

    #pragma unroll 1
    for (int it = 0; it < 8; it++) {
        const int tile = warpGlobal * 8 + it;
        const int m0 = (tile & 31) << 4;
        const int n  = (tile >> 5) & 511;
        const int b  = tile >> 14;

        // ---- build layer1 A fragment: av = sc + sigma^2 * eps ----
        const unsigned short* scB = (const unsigned short*)d_sc
            + ((size_t)(b * 8 + 2 * t) * 512 + n) * 512 + m0;
        unsigned sA  = scB[g];
        unsigned sB_ = scB[262144 + g];
        unsigned sC  = scB[g + 8];
        unsigned sD  = scB[262144 + g + 8];
        uint32_t sc_g  = sA | (sB_ << 16);
        uint32_t sc_g8 = sC | (sD << 16);

        const float* epB = eps + ((size_t)(b * 512 + n) * 512 + m0) * 8 + 2 * t;
        float2 e_g  = *(const float2*)(epB + (size_t)g * 8);
        float2 e_g8 = *(const float2*)(epB + (size_t)(g + 8) * 8);

        __half2 av0 = __hfma2(sig2, __floats2half2_rn(e_g.x,  e_g.y),  *(__half2*)&sc_g);
        __half2 av1 = __hfma2(sig2, __floats2half2_rn(e_g8.x, e_g8.y), *(__half2*)&sc_g8);

        // pad mask: bit0 -> row m0+g, bit1 -> row m0+g+8 (AND over all 8 g-dims)
        unsigned pm = (((sc_g  & 0x7fff7fffu) == 0u) ? 1u : 0u)
                    | (((sc_g8 & 0x7fff7fffu) == 0u) ? 2u : 0u);
        pm &= __shfl_xor_sync(0xffffffffu, pm, 1);
        pm &= __shfl_xor_sync(0xffffffffu, pm, 2);

        // ---- layer1 mma ----
        uint32_t afr[4] = { h2u(av0), h2u(av1), 0u, 0u };
        float h[2][4];
        #pragma unroll
        for (int c = 0; c < 2; c++) {
            h[c][0] = b1v[c][0]; h[c][1] = b1v[c][1];
            h[c][2] = b1v[c][0]; h[c][3] = b1v[c][1];
            uint32_t bfr[2] = { w1f[c], 0u };
            mma16(h[c], afr, bfr);
        }
        // ---- mish ----
        #pragma unroll
        for (int c = 0; c < 2; c++)
            #pragma unroll
            for (int i = 0; i < 4; i++) h[c][i] = mish_f(h[c][i]);

        // ---- layer2 mma (A frag = converted h, identical lane layout) ----
        uint32_t a2f[4];
        a2f[0] = f2h2u(h[0][0], h[0][1]);
        a2f[1] = f2h2u(h[0][2], h[0][3]);
        a2f[2] = f2h2u(h[1][0], h[1][1]);
        a2f[3] = f2h2u(h[1][2], h[1][3]);
        float o2[2][4];
        #pragma unroll
        for (int c = 0; c < 2; c++) {
            o2[c][0] = b2v[c][0]; o2[c][1] = b2v[c][1];
            o2[c][2] = b2v[c][0]; o2[c][3] = b2v[c][1];
            mma16(o2[c], a2f, w2f[c]);
        }

        // ---- logits = o2*SCALE + prior ----
        const float* prB = prior + ((size_t)(b * 16) * 512 + n) * 512 + m0;
        float lg[2][4];
        #pragma unroll
        for (int c = 0; c < 2; c++) {
            const int l0 = 8 * c + 2 * t;
            lg[c][0] = fmaf(o2[c][0], SCALE_F, __ldg(prB + (size_t) l0      * 262144 + g));
            lg[c][1] = fmaf(o2[c][1], SCALE_F, __ldg(prB + (size_t)(l0 + 1) * 262144 + g));
            lg[c][2] = fmaf(o2[c][2], SCALE_F, __ldg(prB + (size_t) l0      * 262144 + g + 8));
            lg[c][3] = fmaf(o2[c][3], SCALE_F, __ldg(prB + (size_t)(l0 + 1) * 262144 + g + 8));
        }

        // ---- softmax over L (16 values spread across the quad of lanes) ----
        // row m0+g:   lg[0][0], lg[0][1], lg[1][0], lg[1][1]  (l = 2t,2t+1,8+2t,9+2t)
        // row m0+g+8: lg[0][2], lg[0][3], lg[1][2], lg[1][3]
        float mx0 = fmaxf(fmaxf(lg[0][0], lg[0][1]), fmaxf(lg[1][0], lg[1][1]));
        mx0 = fmaxf(mx0, __shfl_xor_sync(0xffffffffu, mx0, 1));
        mx0 = fmaxf(mx0, __shfl_xor_sync(0xffffffffu, mx0, 2));
        float mx1 = fmaxf(fmaxf(lg[0][2], lg[0][3]), fmaxf(lg[1][2], lg[1][3]));
        mx1 = fmaxf(mx1, __shfl_xor_sync(0xffffffffu, mx1, 1));
        mx1 = fmaxf(mx1, __shfl_xor_sync(0xffffffffu, mx1, 2));

        float ex[2][4];
        #pragma unroll
        for (int c = 0; c < 2; c++) {
            ex[c][0] = __expf(lg[c][0] - mx0);
            ex[c][1] = __expf(lg[c][1] - mx0);
            ex[c][2] = __expf(lg[c][2] - mx1);
            ex[c][3] = __expf(lg[c][3] - mx1);
        }
        float s0 = (ex[0][0] + ex[0][1]) + (ex[1][0] + ex[1][1]);
        s0 += __shfl_xor_sync(0xffffffffu, s0, 1);
        s0 += __shfl_xor_sync(0xffffffffu, s0, 2);
        float s1 = (ex[0][2] + ex[0][3]) + (ex[1][2] + ex[1][3]);
        s1 += __shfl_xor_sync(0xffffffffu, s1, 1);
        s1 += __shfl_xor_sync(0xffffffffu, s1, 2);
        float inv0 = (pm & 1u) ? 0.0f : __frcp_rn(s0);
        float inv1 = (pm & 2u) ? 0.0f : __frcp_rn(s1);

        // ---- store (compile-time indexed; per-l 8-lane groups form 32B runs) ----
        __half* awB = d_aw + ((size_t)(b * 16) * 512 + n) * 512 + m0;
        #pragma unroll
        for (int c = 0; c < 2; c++) {
            const int l0 = 8 * c + 2 * t;
            awB[(size_t) l0      * 262144 + g]     = __float2half(ex[c][0] * inv0);
            awB[(size_t)(l0 + 1) * 262144 + g]     = __float2half(ex[c][1] * inv0);
            awB[(size_t) l0      * 262144 + g + 8] = __float2half(ex[c][2] * inv1);
            awB[(size_t)(l0 + 1) * 262144 + g + 8] = __float2half(ex[c][3] * inv1);
        }
    }
}

// ---------------------------------------------------------------------------
extern "C" void kernel_launch(void* const* d_in, const int* in_sizes, int n_in,
                              void* d_out, int out_size)
{
    const float* x     = (const float*)d_in[0];
    const float* prior = (const float*)d_in[1];
    const float* eps   = (const float*)d_in[2];
    const float* Wq    = (const float*)d_in[3];
    const float* Wk    = (const float*)d_in[4];
    const float* Wv    = (const float*)d_in[5];
    const float* bv    = (const float*)d_in[6];
    const float* sigma = (const float*)d_in[7];
    const float* Wp1   = (const float*)d_in[8];
    const float* bp1   = (const float*)d_in[9];
    const float* Wp2   = (const float*)d_in[10];
    const float* bp2   = (const float*)d_in[11];
    const float* Wout  = (const float*)d_in[12];
    float* out = (float*)d_out;

    __half *qkv, *sc, *aw, *o, *wqkv, *wouth;
    float* bqkv;
    cudaGetSymbolAddress((void**)&qkv,   d_qkv);
    cudaGetSymbolAddress((void**)&sc,    d_sc);
    cudaGetSymbolAddress((void**)&aw,    d_aw);
    cudaGetSymbolAddress((void**)&o,     d_o);
    cudaGetSymbolAddress((void**)&wqkv,  d_wqkv);
    cudaGetSymbolAddress((void**)&wouth, d_wouth);
    cudaGetSymbolAddress((void**)&bqkv,  d_bqkv);

    const long S   = 512L * 512L;        // 262144
    const long SQ  = 512L * 2048L;       // per-batch qkv stride

    // 0a. MLP weights -> constant bank (D2D, graph-capturable)
    cudaMemcpyToSymbolAsync(cW1,  Wp1,   128 * sizeof(float), 0, cudaMemcpyDeviceToDevice);
    cudaMemcpyToSymbolAsync(cW2,  Wp2,   256 * sizeof(float), 0, cudaMemcpyDeviceToDevice);
    cudaMemcpyToSymbolAsync(cb1,  bp1,    16 * sizeof(float), 0, cudaMemcpyDeviceToDevice);
    cudaMemcpyToSymbolAsync(cb2,  bp2,    16 * sizeof(float), 0, cudaMemcpyDeviceToDevice);
    cudaMemcpyToSymbolAsync(csig, sigma,   8 * sizeof(float), 0, cudaMemcpyDeviceToDevice);

    // 0b. weight prepack (fp32 -> fp16)
    prepack<<<4096, 256>>>(Wq, Wk, Wv, bv, Wout);

    // 1. qkv = x @ [Wq|Wk|Wv] (+bias on v cols)   M=8192 N=2048 K=512
    gemm_h<0, 0, 1><<<dim3(64 * 32, 1), 256>>>(
        x, wqkv, qkv, bqkv,
        8192, 2048, 512, 512, 2048, 2048, 0, 0, 0, 0, 0, 0, 0);

    // 2. scores[b,g] = q_g @ k_g^T   (batch 128)  M=512 N=512 K=64
    gemm_h<1, 1, 1><<<dim3(4 * 8, 128), 256>>>(
        qkv, qkv + 512, sc, nullptr,
        512, 512, 64, 2048, 2048, 512,
        3, SQ, 64, SQ, 64, 8 * S, S);

    // 3. noise + MLP (tensor cores) + prior + softmax(L)
    //    262144 warp-tiles of 16 positions; 8 warps/block, 8 tiles/warp
    k_mid_mma<<<4096, 256>>>(prior, eps);

    // 4. o[b,:,l,:] = aw[b,l] @ v[b,:,l,:]   (batch 256)  M=512 N=64 K=512
    gemm_h<1, 0, 1><<<dim3(4 * 1, 256), 256>>>(
        aw, qkv + 1024, o, nullptr,
        512, 64, 512, 512, 2048, 1024,
        4, 16 * S, S, SQ, 64, 512L * 1024L, 64);

    // 5. out = o @ Wout   M=8192 N=512 K=1024
    gemm_h<1, 0, 0><<<dim3(64 * 8, 1), 256>>>(
        o, wouth, out, nullptr,
        8192, 512, 1024, 1024, 512, 512, 0, 0, 0, 0, 0, 0, 0);
}

// round 14
// speedup vs baseline: 1.4468x; 1.3215x over previous
#include <cuda_runtime.h>
#include <cuda_fp16.h>
#include <stdint.h>

#define NSEQ 512
#define SCALE_F 0.04419417382415922f

// ---------------------------------------------------------------------------
// Scratch (device globals: allocation-free rule)
// ---------------------------------------------------------------------------
__device__ __align__(128) __half d_qkv  [16L * 512 * 1024];       // [b][n][1024]: q|k
__device__ __align__(128) __half d_vT   [16L * 16 * 64 * 512];    // [b][l][d][n]
__device__ __align__(128) __half d_xh   [8192L * 512];            // x in fp16
__device__ __align__(128) __half d_sc   [16L * 8  * 512 * 512];   // [b][g][n][m]
__device__ __align__(128) __half d_aw   [16L * 16 * 512 * 512];   // [b][l][n][m]
__device__ __align__(128) __half d_o    [16L * 512 * 1024];       // [b][n][l*64+d]
__device__ __align__(128) __half d_wqkvT[2048L * 512];            // [c][k]  K-major
__device__ __align__(128) __half d_woutT[512L * 1024];            // [n][k]  K-major

// MLP weights in constant memory
__constant__ float cW1[128];
__constant__ float cW2[256];
__constant__ float cb1[16];
__constant__ float cb2[16];
__constant__ float csig[8];

// ---------------------------------------------------------------------------
__device__ __forceinline__ void mma16(float* c, const uint32_t* a, const uint32_t* b) {
    asm volatile(
        "mma.sync.aligned.m16n8k16.row.col.f32.f16.f16.f32 "
        "{%0,%1,%2,%3}, {%4,%5,%6,%7}, {%8,%9}, {%0,%1,%2,%3};\n"
        : "+f"(c[0]), "+f"(c[1]), "+f"(c[2]), "+f"(c[3])
        : "r"(a[0]), "r"(a[1]), "r"(a[2]), "r"(a[3]), "r"(b[0]), "r"(b[1]));
}
__device__ __forceinline__ uint32_t h2u(__half2 v) { return *(uint32_t*)&v; }
__device__ __forceinline__ uint32_t f2h2u(float lo, float hi) {
    __half2 h = __floats2half2_rn(lo, hi);
    return *(uint32_t*)&h;
}
__device__ __forceinline__ void cp16(void* s, const void* g) {
    uint32_t sa = (uint32_t)__cvta_generic_to_shared(s);
    asm volatile("cp.async.cg.shared.global [%0], [%1], 16;\n" :: "r"(sa), "l"(g));
}
__device__ __forceinline__ void ldm_x4(uint32_t* r, const void* p) {
    uint32_t a = (uint32_t)__cvta_generic_to_shared(p);
    asm volatile("ldmatrix.sync.aligned.m8n8.x4.shared.b16 {%0,%1,%2,%3}, [%4];\n"
        : "=r"(r[0]), "=r"(r[1]), "=r"(r[2]), "=r"(r[3]) : "r"(a));
}

// ---------------------------------------------------------------------------
// Uniform fp16 GEMM: C[M,N] = A[M,K] @ B^T  (A row-major, B K-major [N][K])
// cp.async double-buffered, swizzled smem, ldmatrix fragments.
// Both A and B fragments use NON-trans ldmatrix: for K-major B, lane l of an
// n-row-addressed 8x8 tile holds (n=l/4, k=2(l%4)+{0,1}) = exact .col B frag.
// Tile 128x64, kc=64, 8 warps (4M x 2N), warp tile 32x32.
// EPI: 0 = half C, 1 = float C, 2 = qkv split (q|k -> d_qkv, v -> d_vT + bias)
// ---------------------------------------------------------------------------
template<int EPI>
__global__ __launch_bounds__(256) void gemm_f16(
    const __half* __restrict__ A, const __half* __restrict__ B,
    void* __restrict__ Cv, const float* __restrict__ bias,
    int M, int N, int K, int lda, int ldb, int ldc,
    int innerShift, long sAb, long sAj, long sBb, long sBj, long sCb, long sCj)
{
    __shared__ __align__(16) __half As[2][128 * 64];
    __shared__ __align__(16) __half Bs[2][64 * 64];

    const int tid = threadIdx.x;
    const int tilesN = N >> 6;
    const int tm = blockIdx.x / tilesN, tn = blockIdx.x % tilesN;
    const int row0 = tm * 128, col0 = tn * 64;

    const int z = blockIdx.y;
    const int bb = z >> innerShift, jj = z & ((1 << innerShift) - 1);
    const __half* Ab = A + bb * sAb + jj * sAj;
    const __half* Bb = B + bb * sBb + jj * sBj;

    const int lane = tid & 31, wid = tid >> 5;
    const int wm = wid & 3, wn = wid >> 2;
    const int g = lane >> 2, t = lane & 3;

    const int str = tid >> 3;          // staging row (0..31)
    const int sts = tid & 7;           // staging 16B slice (0..7)

    float c[2][4][4];
    #pragma unroll
    for (int mi = 0; mi < 2; mi++)
        #pragma unroll
        for (int ni = 0; ni < 4; ni++)
            #pragma unroll
            for (int ci = 0; ci < 4; ci++) c[mi][ni][ci] = 0.0f;

    // stage one 64-wide K slab into buffer `buf`
    auto issue_tile = [&](int k0, int buf) {
        #pragma unroll
        for (int i = 0; i < 4; i++) {
            int r = str + i * 32;
            cp16(As[buf] + r * 64 + ((sts ^ (r & 7)) << 3),
                 Ab + (size_t)(row0 + r) * lda + k0 + (sts << 3));
        }
        #pragma unroll
        for (int i = 0; i < 2; i++) {
            int r = str + i * 32;
            cp16(Bs[buf] + r * 64 + ((sts ^ (r & 7)) << 3),
                 Bb + (size_t)(col0 + r) * ldb + k0 + (sts << 3));
        }
        asm volatile("cp.async.commit_group;\n" ::: "memory");
    };

    const int nk = K >> 6;
    issue_tile(0, 0);
    for (int kt = 0; kt < nk; kt++) {
        if (kt + 1 < nk) {
            issue_tile((kt + 1) << 6, (kt + 1) & 1);
            asm volatile("cp.async.wait_group 1;\n" ::: "memory");
        } else {
            asm volatile("cp.async.wait_group 0;\n" ::: "memory");
        }
        __syncthreads();
        const int buf = kt & 1;
        #pragma unroll
        for (int ks = 0; ks < 4; ks++) {
            const int s = ks * 2 + (lane >> 4);
            uint32_t af[2][4];
            #pragma unroll
            for (int mi = 0; mi < 2; mi++) {
                int r = wm * 32 + mi * 16 + (lane & 15);
                ldm_x4(af[mi], As[buf] + r * 64 + ((s ^ (r & 7)) << 3));
            }
            uint32_t bg[2][4];
            #pragma unroll
            for (int nh = 0; nh < 2; nh++) {
                int r = wn * 32 + nh * 16 + (lane & 15);
                ldm_x4(bg[nh], Bs[buf] + r * 64 + ((s ^ (r & 7)) << 3));
            }
            #pragma unroll
            for (int mi = 0; mi < 2; mi++) {
                uint32_t b0[2] = { bg[0][0], bg[0][2] };
                uint32_t b1[2] = { bg[0][1], bg[0][3] };
                uint32_t b2[2] = { bg[1][0], bg[1][2] };
                uint32_t b3[2] = { bg[1][1], bg[1][3] };
                mma16(c[mi][0], af[mi], b0);
                mma16(c[mi][1], af[mi], b1);
                mma16(c[mi][2], af[mi], b2);
                mma16(c[mi][3], af[mi], b3);
            }
        }
        __syncthreads();
    }

    // ---- epilogue ----
    #pragma unroll
    for (int mi = 0; mi < 2; mi++)
        #pragma unroll
        for (int ni = 0; ni < 4; ni++) {
            int row = row0 + wm * 32 + mi * 16 + g;
            int col = col0 + wn * 32 + ni * 8 + 2 * t;
            if (EPI == 2) {
                if (col < 1024) {
                    d_qkv[(size_t)row * 1024 + col] = __float2half(c[mi][ni][0]);
                    d_qkv[(size_t)row * 1024 + col + 1] = __float2half(c[mi][ni][1]);
                    d_qkv[(size_t)(row + 8) * 1024 + col] = __float2half(c[mi][ni][2]);
                    d_qkv[(size_t)(row + 8) * 1024 + col + 1] = __float2half(c[mi][ni][3]);
                } else {
                    int cc = col - 1024;
                    float bv0 = bias[cc], bv1 = bias[cc + 1];
                    int b_ = row >> 9, n_ = row & 511;
                    size_t base = ((size_t)(b_ * 16 + (cc >> 6)) * 64 + (cc & 63)) * 512;
                    d_vT[base + n_]           = __float2half(c[mi][ni][0] + bv0);
                    d_vT[base + 512 + n_]     = __float2half(c[mi][ni][1] + bv1);
                    d_vT[base + n_ + 8]       = __float2half(c[mi][ni][2] + bv0);
                    d_vT[base + 512 + n_ + 8] = __float2half(c[mi][ni][3] + bv1);
                }
            } else if (EPI == 0) {
                __half* Ch = (__half*)Cv + bb * sCb + jj * sCj;
                *(__half2*)(Ch + (size_t)row * ldc + col) =
                    __floats2half2_rn(c[mi][ni][0], c[mi][ni][1]);
                *(__half2*)(Ch + (size_t)(row + 8) * ldc + col) =
                    __floats2half2_rn(c[mi][ni][2], c[mi][ni][3]);
            } else {
                float* Cf = (float*)Cv + bb * sCb + jj * sCj;
                *(float2*)(Cf + (size_t)row * ldc + col) =
                    make_float2(c[mi][ni][0], c[mi][ni][1]);
                *(float2*)(Cf + (size_t)(row + 8) * ldc + col) =
                    make_float2(c[mi][ni][2], c[mi][ni][3]);
            }
        }
}

// ---------------------------------------------------------------------------
// Prepack: x -> fp16; W -> fp16 K-major transposed
// ---------------------------------------------------------------------------
__global__ __launch_bounds__(256) void prepack(
    const float* __restrict__ x,
    const float* __restrict__ Wq, const float* __restrict__ Wk,
    const float* __restrict__ Wv, const float* __restrict__ Wout)
{
    int idx = blockIdx.x * 256 + threadIdx.x;       // 0 .. 4194303
    d_xh[idx] = __float2half(x[idx]);
    if (idx < 2048 * 512) {                          // wqkvT[c][k]
        int cc = idx >> 9, k = idx & 511;
        float v;
        if (cc < 512)       v = Wq[k * 512 + cc];
        else if (cc < 1024) v = Wk[k * 512 + (cc - 512)];
        else                v = Wv[k * 1024 + (cc - 1024)];
        d_wqkvT[idx] = __float2half(v);
    }
    if (idx < 512 * 1024) {                          // woutT[n][k]
        int n = idx >> 10, k = idx & 1023;
        d_woutT[idx] = __float2half(Wout[k * 512 + n]);
    }
}

// ---------------------------------------------------------------------------
// mish(x) = x * (u^2+2u)/(u^2+2u+2), u = e^x
// ---------------------------------------------------------------------------
__device__ __forceinline__ float mish_f(float x) {
    float u = __expf(x);
    float w = fmaf(u, u, 2.0f * u);
    float r = x * w * __frcp_rn(w + 2.0f);
    return (x > 20.0f) ? x : r;
}

// ---------------------------------------------------------------------------
// k_mid_mma: noise + head-mix MLP on tensor cores + prior + softmax(L)
// (unchanged from R10 passing version)
// ---------------------------------------------------------------------------
__global__ __launch_bounds__(256) void k_mid_mma(
    const float* __restrict__ prior, const float* __restrict__ eps)
{
    const int lane = threadIdx.x & 31;
    const int g = lane >> 2, t = lane & 3;
    const int warpGlobal = (blockIdx.x << 3) + (threadIdx.x >> 5);

    uint32_t w1f[2], w2f[2][2];
    float b1v[2][2], b2v[2][2];
    #pragma unroll
    for (int c = 0; c < 2; c++) {
        w1f[c]    = f2h2u(cW1[(2*t)  *16 + 8*c + g], cW1[(2*t+1)*16 + 8*c + g]);
        w2f[c][0] = f2h2u(cW2[(2*t)  *16 + 8*c + g], cW2[(2*t+1)*16 + 8*c + g]);
        w2f[c][1] = f2h2u(cW2[(2*t+8)*16 + 8*c + g], cW2[(2*t+9)*16 + 8*c + g]);
        b1v[c][0] = cb1[8*c + 2*t]; b1v[c][1] = cb1[8*c + 2*t + 1];
        b2v[c][0] = cb2[8*c + 2*t]; b2v[c][1] = cb2[8*c + 2*t + 1];
    }
    const float sg0 = csig[2*t], sg1 = csig[2*t+1];
    const __half2 sig2 = __floats2half2_rn(sg0 * sg0, sg1 * sg1);

    #pragma unroll 1
    for (int it = 0; it < 8; it++) {
        const int tile = warpGlobal * 8 + it;
        const int m0 = (tile & 31) << 4;
        const int n  = (tile >> 5) & 511;
        const int b  = tile >> 14;

        const unsigned short* scB = (const unsigned short*)d_sc
            + ((size_t)(b * 8 + 2 * t) * 512 + n) * 512 + m0;
        unsigned sA  = scB[g];
        unsigned sB_ = scB[262144 + g];
        unsigned sC  = scB[g + 8];
        unsigned sD  = scB[262144 + g + 8];
        uint32_t sc_g  = sA | (sB_ << 16);
        uint32_t sc_g8 = sC | (sD << 16);

        const float* epB = eps + ((size_t)(b * 512 + n) * 512 + m0) * 8 + 2 * t;
        float2 e_g  = *(const float2*)(epB + (size_t)g * 8);
        float2 e_g8 = *(const float2*)(epB + (size_t)(g + 8) * 8);

        __half2 av0 = __hfma2(sig2, __floats2half2_rn(e_g.x,  e_g.y),  *(__half2*)&sc_g);
        __half2 av1 = __hfma2(sig2, __floats2half2_rn(e_g8.x, e_g8.y), *(__half2*)&sc_g8);

        unsigned pm = (((sc_g  & 0x7fff7fffu) == 0u) ? 1u : 0u)
                    | (((sc_g8 & 0x7fff7fffu) == 0u) ? 2u : 0u);
        pm &= __shfl_xor_sync(0xffffffffu, pm, 1);
        pm &= __shfl_xor_sync(0xffffffffu, pm, 2);

        uint32_t afr[4] = { h2u(av0), h2u(av1), 0u, 0u };
        float h[2][4];
        #pragma unroll
        for (int c = 0; c < 2; c++) {
            h[c][0] = b1v[c][0]; h[c][1] = b1v[c][1];
            h[c][2] = b1v[c][0]; h[c][3] = b1v[c][1];
            uint32_t bfr[2] = { w1f[c], 0u };
            mma16(h[c], afr, bfr);
        }
        #pragma unroll
        for (int c = 0; c < 2; c++)
            #pragma unroll
            for (int i = 0; i < 4; i++) h[c][i] = mish_f(h[c][i]);

        uint32_t a2f[4];
        a2f[0] = f2h2u(h[0][0], h[0][1]);
        a2f[1] = f2h2u(h[0][2], h[0][3]);
        a2f[2] = f2h2u(h[1][0], h[1][1]);
        a2f[3] = f2h2u(h[1][2], h[1][3]);
        float o2[2][4];
        #pragma unroll
        for (int c = 0; c < 2; c++) {
            o2[c][0] = b2v[c][0]; o2[c][1] = b2v[c][1];
            o2[c][2] = b2v[c][0]; o2[c][3] = b2v[c][1];
            mma16(o2[c], a2f, w2f[c]);
        }

        const float* prB = prior + ((size_t)(b * 16) * 512 + n) * 512 + m0;
        float lg[2][4];
        #pragma unroll
        for (int c = 0; c < 2; c++) {
            const int l0 = 8 * c + 2 * t;
            lg[c][0] = fmaf(o2[c][0], SCALE_F, __ldg(prB + (size_t) l0      * 262144 + g));
            lg[c][1] = fmaf(o2[c][1], SCALE_F, __ldg(prB + (size_t)(l0 + 1) * 262144 + g));
            lg[c][2] = fmaf(o2[c][2], SCALE_F, __ldg(prB + (size_t) l0      * 262144 + g + 8));
            lg[c][3] = fmaf(o2[c][3], SCALE_F, __ldg(prB + (size_t)(l0 + 1) * 262144 + g + 8));
        }

        float mx0 = fmaxf(fmaxf(lg[0][0], lg[0][1]), fmaxf(lg[1][0], lg[1][1]));
        mx0 = fmaxf(mx0, __shfl_xor_sync(0xffffffffu, mx0, 1));
        mx0 = fmaxf(mx0, __shfl_xor_sync(0xffffffffu, mx0, 2));
        float mx1 = fmaxf(fmaxf(lg[0][2], lg[0][3]), fmaxf(lg[1][2], lg[1][3]));
        mx1 = fmaxf(mx1, __shfl_xor_sync(0xffffffffu, mx1, 1));
        mx1 = fmaxf(mx1, __shfl_xor_sync(0xffffffffu, mx1, 2));

        float ex[2][4];
        #pragma unroll
        for (int c = 0; c < 2; c++) {
            ex[c][0] = __expf(lg[c][0] - mx0);
            ex[c][1] = __expf(lg[c][1] - mx0);
            ex[c][2] = __expf(lg[c][2] - mx1);
            ex[c][3] = __expf(lg[c][3] - mx1);
        }
        float s0 = (ex[0][0] + ex[0][1]) + (ex[1][0] + ex[1][1]);
        s0 += __shfl_xor_sync(0xffffffffu, s0, 1);
        s0 += __shfl_xor_sync(0xffffffffu, s0, 2);
        float s1 = (ex[0][2] + ex[0][3]) + (ex[1][2] + ex[1][3]);
        s1 += __shfl_xor_sync(0xffffffffu, s1, 1);
        s1 += __shfl_xor_sync(0xffffffffu, s1, 2);
        float inv0 = (pm & 1u) ? 0.0f : __frcp_rn(s0);
        float inv1 = (pm & 2u) ? 0.0f : __frcp_rn(s1);

        __half* awB = d_aw + ((size_t)(b * 16) * 512 + n) * 512 + m0;
        #pragma unroll
        for (int c = 0; c < 2; c++) {
            const int l0 = 8 * c + 2 * t;
            awB[(size_t) l0      * 262144 + g]     = __float2half(ex[c][0] * inv0);
            awB[(size_t)(l0 + 1) * 262144 + g]     = __float2half(ex[c][1] * inv0);
            awB[(size_t) l0      * 262144 + g + 8] = __float2half(ex[c][2] * inv1);
            awB[(size_t)(l0 + 1) * 262144 + g + 8] = __float2half(ex[c][3] * inv1);
        }
    }
}

// ---------------------------------------------------------------------------
extern "C" void kernel_launch(void* const* d_in, const int* in_sizes, int n_in,
                              void* d_out, int out_size)
{
    const float* x     = (const float*)d_in[0];
    const float* prior = (const float*)d_in[1];
    const float* eps   = (const float*)d_in[2];
    const float* Wq    = (const float*)d_in[3];
    const float* Wk    = (const float*)d_in[4];
    const float* Wv    = (const float*)d_in[5];
    const float* bv    = (const float*)d_in[6];
    const float* sigma = (const float*)d_in[7];
    const float* Wp1   = (const float*)d_in[8];
    const float* bp1   = (const float*)d_in[9];
    const float* Wp2   = (const float*)d_in[10];
    const float* bp2   = (const float*)d_in[11];
    const float* Wout  = (const float*)d_in[12];
    float* out = (float*)d_out;

    __half *qkv, *vT, *xh, *sc, *aw, *o, *wqkvT, *woutT;
    cudaGetSymbolAddress((void**)&qkv,   d_qkv);
    cudaGetSymbolAddress((void**)&vT,    d_vT);
    cudaGetSymbolAddress((void**)&xh,    d_xh);
    cudaGetSymbolAddress((void**)&sc,    d_sc);
    cudaGetSymbolAddress((void**)&aw,    d_aw);
    cudaGetSymbolAddress((void**)&o,     d_o);
    cudaGetSymbolAddress((void**)&wqkvT, d_wqkvT);
    cudaGetSymbolAddress((void**)&woutT, d_woutT);

    const long S   = 512L * 512L;       // 262144
    const long SQK = 512L * 1024L;      // per-batch q|k stride

    cudaMemcpyToSymbolAsync(cW1,  Wp1,   128 * sizeof(float), 0, cudaMemcpyDeviceToDevice);
    cudaMemcpyToSymbolAsync(cW2,  Wp2,   256 * sizeof(float), 0, cudaMemcpyDeviceToDevice);
    cudaMemcpyToSymbolAsync(cb1,  bp1,    16 * sizeof(float), 0, cudaMemcpyDeviceToDevice);
    cudaMemcpyToSymbolAsync(cb2,  bp2,    16 * sizeof(float), 0, cudaMemcpyDeviceToDevice);
    cudaMemcpyToSymbolAsync(csig, sigma,   8 * sizeof(float), 0, cudaMemcpyDeviceToDevice);

    // 0. prepack (x->fp16, weights transposed fp16)
    prepack<<<16384, 256>>>(x, Wq, Wk, Wv, Wout);

    // 1. qkv: M=8192 N=2048 K=512; q|k -> d_qkv, v -> d_vT (+bias)
    gemm_f16<2><<<dim3(64 * 32, 1), 256>>>(
        xh, wqkvT, nullptr, bv,
        8192, 2048, 512, 512, 512, 0, 0, 0, 0, 0, 0, 0, 0);

    // 2. scores[b,g] = q_g @ k_g^T   (batch 128)  M=512 N=512 K=64
    gemm_f16<0><<<dim3(4 * 8, 128), 256>>>(
        qkv, qkv + 512, sc, nullptr,
        512, 512, 64, 1024, 1024, 512,
        3, SQK, 64, SQK, 64, 8 * S, S);

    // 3. noise + MLP + prior + softmax(L)
    k_mid_mma<<<4096, 256>>>(prior, eps);

    // 4. o[b,:,l,:] = aw[b,l] @ vT[b,l]^T   (batch 256)  M=512 N=64 K=512
    gemm_f16<0><<<dim3(4, 256), 256>>>(
        aw, vT, o, nullptr,
        512, 64, 512, 512, 512, 1024,
        4, 16 * S, S, 16L * 32768, 32768, 512L * 1024, 64);

    // 5. out = o @ Wout   M=8192 N=512 K=1024
    gemm_f16<1><<<dim3(64 * 8, 1), 256>>>(
        o, woutT, out, nullptr,
        8192, 512, 1024, 1024, 1024, 512,
        0, 0, 0, 0, 0, 0, 0);
}